// round 12
// baseline (speedup 1.0000x reference)
#include <cuda_runtime.h>
#include <cuda_fp16.h>
#include <cstdint>

// LightAggregator: bidirectional COO scatter-add as bucket-gather with
// fp16-compressed embedding reads and half2 inner-loop arithmetic
// (fp32 accumulation flushed every 4 edges).  [Round-10 structure — fastest
// measured — plus __launch_bounds__(256,8) on gather to lift occupancy.]
//   entity_agg[c] = sum over edges (r,c,v): v * user_emb[r]
//   user_agg[r]   = sum over edges (r,c,v): v * entity_emb[c]
// Phase 1 (one kernel): scatter edges into fixed-capacity per-segment buckets
// (1 cursor atomic per entry) AND convert both embedding tables to fp16.
// Phase 2: gather — half-warp per segment, 4-edge HFMA2 chains, fp32 flush.
// Overflow (statistically ~never at these degree caps) folded into gather.
//
// Inputs: d_in[0] user_emb f32[NU*64], d_in[1] entity_emb f32[NE*64],
//         d_in[2] rows i32[NNZ], d_in[3] cols i32[NNZ], d_in[4] vals f32[NNZ]
// Output: entity_agg [NE*64] ++ user_agg [NU*64], f32.

static constexpr int D  = 64;
static constexpr int D4 = D / 4;

static constexpr int MAX_NE = 50048;
static constexpr int MAX_NU = 100096;
static constexpr int ECAP = 128;    // entity degree: mean 40, tail ~70
static constexpr int UCAP = 64;     // user degree: mean 20, tail ~50
static constexpr int MAX_OVF = 8192;

__device__ int    g_ecnt[MAX_NE];
__device__ int    g_ucnt[MAX_NU];
__device__ float2 g_ebkt[(size_t)MAX_NE * ECAP];   // (user_idx bits, val)
__device__ float2 g_ubkt[(size_t)MAX_NU * UCAP];   // (entity_idx bits, val)
__device__ int    g_ovf_cnt;
__device__ float4 g_ovf[MAX_OVF];   // (seg | is_user<<30, nbr, val, unused)
// fp16 embeddings: one uint2 = 4 halves; row = 16 uint2 = 128 B.
__device__ uint2  g_uemb16[(size_t)MAX_NU * 16];
__device__ uint2  g_eemb16[(size_t)MAX_NE * 16];

__device__ __forceinline__ unsigned pack_h2(float a, float b) {
    __half2 h = __floats2half2_rn(a, b);
    return *reinterpret_cast<unsigned*>(&h);
}
__device__ __forceinline__ float2 unpack_h2(unsigned u) {
    __half2 h = *reinterpret_cast<__half2*>(&u);
    return __half22float2(h);
}
__device__ __forceinline__ __half2 as_h2(unsigned u) {
    return *reinterpret_cast<__half2*>(&u);
}

// ---------- phase 1: scatter (1 edge/thread) + fp16 convert, one grid ----------

__global__ void scatter_convert_kernel(const int* __restrict__ rows,
                                       const int* __restrict__ cols,
                                       const float* __restrict__ vals,
                                       int nnz,
                                       const float4* __restrict__ user_emb,
                                       const float4* __restrict__ entity_emb,
                                       int nu16, int ne16, int edge_blocks) {
    int tid = threadIdx.x;
    int b = blockIdx.x;
    if (b < edge_blocks) {
        int e = b * blockDim.x + tid;
        if (e >= nnz) return;
        int r = rows[e];
        int c = cols[e];
        float v = vals[e];

        int p = atomicAdd(&g_ecnt[c], 1);
        if (p < ECAP) {
            g_ebkt[(size_t)c * ECAP + p] = make_float2(__int_as_float(r), v);
        } else {
            int o = atomicAdd(&g_ovf_cnt, 1);
            if (o < MAX_OVF)
                g_ovf[o] = make_float4(__int_as_float(c), __int_as_float(r), v, 0.f);
        }

        int q = atomicAdd(&g_ucnt[r], 1);
        if (q < UCAP) {
            g_ubkt[(size_t)r * UCAP + q] = make_float2(__int_as_float(c), v);
        } else {
            int o = atomicAdd(&g_ovf_cnt, 1);
            if (o < MAX_OVF)
                g_ovf[o] = make_float4(__int_as_float(r | (1 << 30)), __int_as_float(c), v, 0.f);
        }
    } else {
        // Convert blocks: i indexes float4 quartets across user then entity.
        int i = (b - edge_blocks) * blockDim.x + tid;
        if (i < nu16) {
            float4 x = user_emb[i];
            g_uemb16[i] = make_uint2(pack_h2(x.x, x.y), pack_h2(x.z, x.w));
        } else {
            int j = i - nu16;
            if (j < ne16) {
                float4 x = entity_emb[j];
                g_eemb16[j] = make_uint2(pack_h2(x.x, x.y), pack_h2(x.z, x.w));
            }
        }
    }
}

// ---------- phase 2: gather ----------
// Half-warp per segment; lane owns 4 dims = one uint2 (8B) of the fp16 row.
// 4-edge chunks: two independent HFMA2 chains (edges 0,2 / 1,3), hadd2 merge,
// fp32 flush. Tail and overflow in fp32.
// __launch_bounds__(256, 8): cap regs at 32 so 8 blocks/SM (full 2048 threads)
// fit — the round-10 measurement was register-limited at occ 62%.

__global__ void __launch_bounds__(256, 8)
gather_kernel(float4* __restrict__ entity_agg,
              float4* __restrict__ user_agg,
              int n_seg, int ne) {
    int gid  = blockIdx.x * blockDim.x + threadIdx.x;
    int s    = gid >> 4;
    int lane = gid & 15;
    if (s >= n_seg) return;

    const float2* __restrict__ bkt;
    const uint2* __restrict__ src16;
    float4* dst;
    int cnt;
    int my_tag;
    if (s < ne) {
        cnt = g_ecnt[s];
        if (cnt > ECAP) cnt = ECAP;
        bkt = g_ebkt + (size_t)s * ECAP;
        src16 = g_uemb16;
        dst = entity_agg + (long long)s * D4;
        my_tag = s;
    } else {
        int u = s - ne;
        cnt = g_ucnt[u];
        if (cnt > UCAP) cnt = UCAP;
        bkt = g_ubkt + (size_t)u * UCAP;
        src16 = g_eemb16;
        dst = user_agg + (long long)u * D4;
        my_tag = u | (1 << 30);
    }

    float4 acc0 = make_float4(0.f, 0.f, 0.f, 0.f);
    int i = 0;
    for (; i + 3 < cnt; i += 4) {
        float2 e0 = bkt[i];
        float2 e1 = bkt[i + 1];
        float2 e2 = bkt[i + 2];
        float2 e3 = bkt[i + 3];
        uint2 x0 = src16[(size_t)__float_as_int(e0.x) * 16 + lane];
        uint2 x1 = src16[(size_t)__float_as_int(e1.x) * 16 + lane];
        uint2 x2 = src16[(size_t)__float_as_int(e2.x) * 16 + lane];
        uint2 x3 = src16[(size_t)__float_as_int(e3.x) * 16 + lane];

        __half2 v0 = __float2half2_rn(e0.y);
        __half2 v1 = __float2half2_rn(e1.y);
        __half2 v2 = __float2half2_rn(e2.y);
        __half2 v3 = __float2half2_rn(e3.y);

        // dims 0-1: two independent 2-term chains, merge, flush.
        __half2 a_lo = __hmul2(v0, as_h2(x0.x));
        __half2 b_lo = __hmul2(v1, as_h2(x1.x));
        a_lo = __hfma2(v2, as_h2(x2.x), a_lo);
        b_lo = __hfma2(v3, as_h2(x3.x), b_lo);
        a_lo = __hadd2(a_lo, b_lo);
        float2 f_lo = __half22float2(a_lo);
        acc0.x += f_lo.x;
        acc0.y += f_lo.y;

        // dims 2-3.
        __half2 a_hi = __hmul2(v0, as_h2(x0.y));
        __half2 b_hi = __hmul2(v1, as_h2(x1.y));
        a_hi = __hfma2(v2, as_h2(x2.y), a_hi);
        b_hi = __hfma2(v3, as_h2(x3.y), b_hi);
        a_hi = __hadd2(a_hi, b_hi);
        float2 f_hi = __half22float2(a_hi);
        acc0.z += f_hi.x;
        acc0.w += f_hi.y;
    }
    for (; i < cnt; i++) {
        float2 e0 = bkt[i];
        uint2 x0 = src16[(size_t)__float_as_int(e0.x) * 16 + lane];
        float2 a = unpack_h2(x0.x), bq = unpack_h2(x0.y);
        acc0.x = fmaf(e0.y, a.x,  acc0.x);
        acc0.y = fmaf(e0.y, a.y,  acc0.y);
        acc0.z = fmaf(e0.y, bq.x, acc0.z);
        acc0.w = fmaf(e0.y, bq.y, acc0.w);
    }

    // Inline overflow fixup: one broadcast load; body never runs in practice.
    int novf = g_ovf_cnt;
    if (novf > 0) {
        if (novf > MAX_OVF) novf = MAX_OVF;
        for (int o = 0; o < novf; o++) {
            float4 rec = g_ovf[o];
            if (__float_as_int(rec.x) == my_tag) {
                uint2 x = src16[(size_t)__float_as_int(rec.y) * 16 + lane];
                float2 a = unpack_h2(x.x), bq = unpack_h2(x.y);
                acc0.x = fmaf(rec.z, a.x,  acc0.x);
                acc0.y = fmaf(rec.z, a.y,  acc0.y);
                acc0.z = fmaf(rec.z, bq.x, acc0.z);
                acc0.w = fmaf(rec.z, bq.y, acc0.w);
            }
        }
    }

    dst[lane] = acc0;
}

// ---------- launch ----------

extern "C" void kernel_launch(void* const* d_in, const int* in_sizes, int n_in,
                              void* d_out, int out_size) {
    const float4* user_emb   = (const float4*)d_in[0];
    const float4* entity_emb = (const float4*)d_in[1];
    const int*    rows       = (const int*)d_in[2];
    const int*    cols       = (const int*)d_in[3];
    const float*  vals       = (const float*)d_in[4];

    int nu  = in_sizes[0] / D;
    int ne  = in_sizes[1] / D;
    int nnz = in_sizes[2];
    int n_seg = ne + nu;

    float* out = (float*)d_out;
    float4* entity_agg = (float4*)out;
    float4* user_agg   = (float4*)(out + (long long)ne * D);

    // Counter init via memset nodes (capture-legal, no allocation).
    void *p_ecnt = nullptr, *p_ucnt = nullptr, *p_ovf = nullptr;
    cudaGetSymbolAddress(&p_ecnt, g_ecnt);
    cudaGetSymbolAddress(&p_ucnt, g_ucnt);
    cudaGetSymbolAddress(&p_ovf,  g_ovf_cnt);
    cudaMemsetAsync(p_ecnt, 0, (size_t)ne * sizeof(int));
    cudaMemsetAsync(p_ucnt, 0, (size_t)nu * sizeof(int));
    cudaMemsetAsync(p_ovf,  0, sizeof(int));

    int T = 256;
    int edge_blocks = (nnz + T - 1) / T;
    int nu16 = nu * 16, ne16 = ne * 16;
    int conv_blocks = (nu16 + ne16 + T - 1) / T;
    scatter_convert_kernel<<<edge_blocks + conv_blocks, T>>>(
        rows, cols, vals, nnz, user_emb, entity_emb, nu16, ne16, edge_blocks);

    long long total_threads = (long long)n_seg * 16;
    int gather_blocks = (int)((total_threads + T - 1) / T);
    gather_kernel<<<gather_blocks, T>>>(entity_agg, user_agg, n_seg, ne);
}

// round 14
// speedup vs baseline: 1.1836x; 1.1836x over previous
#include <cuda_runtime.h>
#include <cuda_fp16.h>
#include <cstdint>

// LightAggregator: bidirectional COO scatter-add as bucket-gather with
// fp16-compressed embedding reads and half2 inner-loop arithmetic
// (fp32 accumulation flushed every 4 edges).  [Round-10 structure — fastest
// measured — with scatter/convert block roles INTERLEAVED so the DRAM-bound
// table conversion overlaps the atomic-latency-bound edge scatter in every
// dispatch wave instead of running serially after it.]
//   entity_agg[c] = sum over edges (r,c,v): v * user_emb[r]
//   user_agg[r]   = sum over edges (r,c,v): v * entity_emb[c]
//
// Inputs: d_in[0] user_emb f32[NU*64], d_in[1] entity_emb f32[NE*64],
//         d_in[2] rows i32[NNZ], d_in[3] cols i32[NNZ], d_in[4] vals f32[NNZ]
// Output: entity_agg [NE*64] ++ user_agg [NU*64], f32.

static constexpr int D  = 64;
static constexpr int D4 = D / 4;

static constexpr int MAX_NE = 50048;
static constexpr int MAX_NU = 100096;
static constexpr int ECAP = 128;    // entity degree: mean 40, tail ~70
static constexpr int UCAP = 64;     // user degree: mean 20, tail ~50
static constexpr int MAX_OVF = 8192;

__device__ int    g_ecnt[MAX_NE];
__device__ int    g_ucnt[MAX_NU];
__device__ float2 g_ebkt[(size_t)MAX_NE * ECAP];   // (user_idx bits, val)
__device__ float2 g_ubkt[(size_t)MAX_NU * UCAP];   // (entity_idx bits, val)
__device__ int    g_ovf_cnt;
__device__ float4 g_ovf[MAX_OVF];   // (seg | is_user<<30, nbr, val, unused)
// fp16 embeddings: one uint2 = 4 halves; row = 16 uint2 = 128 B.
__device__ uint2  g_uemb16[(size_t)MAX_NU * 16];
__device__ uint2  g_eemb16[(size_t)MAX_NE * 16];

__device__ __forceinline__ unsigned pack_h2(float a, float b) {
    __half2 h = __floats2half2_rn(a, b);
    return *reinterpret_cast<unsigned*>(&h);
}
__device__ __forceinline__ float2 unpack_h2(unsigned u) {
    __half2 h = *reinterpret_cast<__half2*>(&u);
    return __half22float2(h);
}
__device__ __forceinline__ __half2 as_h2(unsigned u) {
    return *reinterpret_cast<__half2*>(&u);
}

// ---------- phase 1: scatter + fp16 convert, roles interleaved ----------
// Block b is an edge block iff floor((b+1)*EB/TB) > floor(b*EB/TB); this
// yields exactly EB edge blocks spread evenly through the dispatch order,
// with unique dense sub-indices for both roles.

__global__ void scatter_convert_kernel(const int* __restrict__ rows,
                                       const int* __restrict__ cols,
                                       const float* __restrict__ vals,
                                       int nnz,
                                       const float4* __restrict__ user_emb,
                                       const float4* __restrict__ entity_emb,
                                       int nu16, int ne16,
                                       int edge_blocks, int total_blocks) {
    int tid = threadIdx.x;
    int b = blockIdx.x;
    long long eidx  = ((long long)b * edge_blocks) / total_blocks;
    long long enext = ((long long)(b + 1) * edge_blocks) / total_blocks;
    if (enext > eidx) {
        // ---- edge block #eidx ----
        int e = (int)eidx * blockDim.x + tid;
        if (e >= nnz) return;
        int r = rows[e];
        int c = cols[e];
        float v = vals[e];

        int p = atomicAdd(&g_ecnt[c], 1);
        if (p < ECAP) {
            g_ebkt[(size_t)c * ECAP + p] = make_float2(__int_as_float(r), v);
        } else {
            int o = atomicAdd(&g_ovf_cnt, 1);
            if (o < MAX_OVF)
                g_ovf[o] = make_float4(__int_as_float(c), __int_as_float(r), v, 0.f);
        }

        int q = atomicAdd(&g_ucnt[r], 1);
        if (q < UCAP) {
            g_ubkt[(size_t)r * UCAP + q] = make_float2(__int_as_float(c), v);
        } else {
            int o = atomicAdd(&g_ovf_cnt, 1);
            if (o < MAX_OVF)
                g_ovf[o] = make_float4(__int_as_float(r | (1 << 30)), __int_as_float(c), v, 0.f);
        }
    } else {
        // ---- convert block #(b - enext) ----
        int cb = b - (int)enext;
        int i = cb * blockDim.x + tid;
        if (i < nu16) {
            float4 x = user_emb[i];
            g_uemb16[i] = make_uint2(pack_h2(x.x, x.y), pack_h2(x.z, x.w));
        } else {
            int j = i - nu16;
            if (j < ne16) {
                float4 x = entity_emb[j];
                g_eemb16[j] = make_uint2(pack_h2(x.x, x.y), pack_h2(x.z, x.w));
            }
        }
    }
}

// ---------- phase 2: gather (byte-identical to round 10) ----------
// Half-warp per segment; lane owns 4 dims = one uint2 (8B) of the fp16 row.
// 4-edge chunks: two independent HFMA2 chains (edges 0,2 / 1,3), hadd2 merge,
// fp32 flush. Tail and overflow in fp32.

__global__ void __launch_bounds__(256)
gather_kernel(float4* __restrict__ entity_agg,
              float4* __restrict__ user_agg,
              int n_seg, int ne) {
    int gid  = blockIdx.x * blockDim.x + threadIdx.x;
    int s    = gid >> 4;
    int lane = gid & 15;
    if (s >= n_seg) return;

    const float2* __restrict__ bkt;
    const uint2* __restrict__ src16;
    float4* dst;
    int cnt;
    int my_tag;
    if (s < ne) {
        cnt = g_ecnt[s];
        if (cnt > ECAP) cnt = ECAP;
        bkt = g_ebkt + (size_t)s * ECAP;
        src16 = g_uemb16;
        dst = entity_agg + (long long)s * D4;
        my_tag = s;
    } else {
        int u = s - ne;
        cnt = g_ucnt[u];
        if (cnt > UCAP) cnt = UCAP;
        bkt = g_ubkt + (size_t)u * UCAP;
        src16 = g_eemb16;
        dst = user_agg + (long long)u * D4;
        my_tag = u | (1 << 30);
    }

    float4 acc0 = make_float4(0.f, 0.f, 0.f, 0.f);
    int i = 0;
    for (; i + 3 < cnt; i += 4) {
        float2 e0 = bkt[i];
        float2 e1 = bkt[i + 1];
        float2 e2 = bkt[i + 2];
        float2 e3 = bkt[i + 3];
        uint2 x0 = src16[(size_t)__float_as_int(e0.x) * 16 + lane];
        uint2 x1 = src16[(size_t)__float_as_int(e1.x) * 16 + lane];
        uint2 x2 = src16[(size_t)__float_as_int(e2.x) * 16 + lane];
        uint2 x3 = src16[(size_t)__float_as_int(e3.x) * 16 + lane];

        __half2 v0 = __float2half2_rn(e0.y);
        __half2 v1 = __float2half2_rn(e1.y);
        __half2 v2 = __float2half2_rn(e2.y);
        __half2 v3 = __float2half2_rn(e3.y);

        // dims 0-1: two independent 2-term chains, merge, flush.
        __half2 a_lo = __hmul2(v0, as_h2(x0.x));
        __half2 b_lo = __hmul2(v1, as_h2(x1.x));
        a_lo = __hfma2(v2, as_h2(x2.x), a_lo);
        b_lo = __hfma2(v3, as_h2(x3.x), b_lo);
        a_lo = __hadd2(a_lo, b_lo);
        float2 f_lo = __half22float2(a_lo);
        acc0.x += f_lo.x;
        acc0.y += f_lo.y;

        // dims 2-3.
        __half2 a_hi = __hmul2(v0, as_h2(x0.y));
        __half2 b_hi = __hmul2(v1, as_h2(x1.y));
        a_hi = __hfma2(v2, as_h2(x2.y), a_hi);
        b_hi = __hfma2(v3, as_h2(x3.y), b_hi);
        a_hi = __hadd2(a_hi, b_hi);
        float2 f_hi = __half22float2(a_hi);
        acc0.z += f_hi.x;
        acc0.w += f_hi.y;
    }
    for (; i < cnt; i++) {
        float2 e0 = bkt[i];
        uint2 x0 = src16[(size_t)__float_as_int(e0.x) * 16 + lane];
        float2 a = unpack_h2(x0.x), bq = unpack_h2(x0.y);
        acc0.x = fmaf(e0.y, a.x,  acc0.x);
        acc0.y = fmaf(e0.y, a.y,  acc0.y);
        acc0.z = fmaf(e0.y, bq.x, acc0.z);
        acc0.w = fmaf(e0.y, bq.y, acc0.w);
    }

    // Inline overflow fixup: one broadcast load; body never runs in practice.
    int novf = g_ovf_cnt;
    if (novf > 0) {
        if (novf > MAX_OVF) novf = MAX_OVF;
        for (int o = 0; o < novf; o++) {
            float4 rec = g_ovf[o];
            if (__float_as_int(rec.x) == my_tag) {
                uint2 x = src16[(size_t)__float_as_int(rec.y) * 16 + lane];
                float2 a = unpack_h2(x.x), bq = unpack_h2(x.y);
                acc0.x = fmaf(rec.z, a.x,  acc0.x);
                acc0.y = fmaf(rec.z, a.y,  acc0.y);
                acc0.z = fmaf(rec.z, bq.x, acc0.z);
                acc0.w = fmaf(rec.z, bq.y, acc0.w);
            }
        }
    }

    dst[lane] = acc0;
}

// ---------- launch ----------

extern "C" void kernel_launch(void* const* d_in, const int* in_sizes, int n_in,
                              void* d_out, int out_size) {
    const float4* user_emb   = (const float4*)d_in[0];
    const float4* entity_emb = (const float4*)d_in[1];
    const int*    rows       = (const int*)d_in[2];
    const int*    cols       = (const int*)d_in[3];
    const float*  vals       = (const float*)d_in[4];

    int nu  = in_sizes[0] / D;
    int ne  = in_sizes[1] / D;
    int nnz = in_sizes[2];
    int n_seg = ne + nu;

    float* out = (float*)d_out;
    float4* entity_agg = (float4*)out;
    float4* user_agg   = (float4*)(out + (long long)ne * D);

    // Counter init via memset nodes (capture-legal, no allocation).
    void *p_ecnt = nullptr, *p_ucnt = nullptr, *p_ovf = nullptr;
    cudaGetSymbolAddress(&p_ecnt, g_ecnt);
    cudaGetSymbolAddress(&p_ucnt, g_ucnt);
    cudaGetSymbolAddress(&p_ovf,  g_ovf_cnt);
    cudaMemsetAsync(p_ecnt, 0, (size_t)ne * sizeof(int));
    cudaMemsetAsync(p_ucnt, 0, (size_t)nu * sizeof(int));
    cudaMemsetAsync(p_ovf,  0, sizeof(int));

    int T = 256;
    int edge_blocks = (nnz + T - 1) / T;
    int nu16 = nu * 16, ne16 = ne * 16;
    int conv_blocks = (nu16 + ne16 + T - 1) / T;
    int total_blocks = edge_blocks + conv_blocks;
    scatter_convert_kernel<<<total_blocks, T>>>(
        rows, cols, vals, nnz, user_emb, entity_emb, nu16, ne16,
        edge_blocks, total_blocks);

    long long total_threads = (long long)n_seg * 16;
    int gather_blocks = (int)((total_threads + T - 1) / T);
    gather_kernel<<<gather_blocks, T>>>(entity_agg, user_agg, n_seg, ne);
}

// round 15
// speedup vs baseline: 1.2212x; 1.0317x over previous
#include <cuda_runtime.h>
#include <cuda_fp16.h>
#include <cstdint>

// LightAggregator: bidirectional COO scatter-add as bucket-gather with
// fp16-compressed embedding reads and half2 inner-loop arithmetic
// (fp32 accumulation flushed every 4 edges).
//   entity_agg[c] = sum over edges (r,c,v): v * user_emb[r]
//   user_agg[r]   = sum over edges (r,c,v): v * entity_emb[c]
// Phase 1: scatter edges into fixed-capacity buckets + fp16 table convert,
// block roles interleaved across the dispatch order (overlap atomic-latency
// work with DRAM-streaming work in every wave).
// Phase 2: gather — 8 lanes per segment, each lane owns 8 dims (one uint4 of
// the fp16 row, LDG.128): halves per-segment load-issue and loop overhead vs
// the 16-lane layout while keeping bytes and per-dim HFMA2 work identical.
//
// Inputs: d_in[0] user_emb f32[NU*64], d_in[1] entity_emb f32[NE*64],
//         d_in[2] rows i32[NNZ], d_in[3] cols i32[NNZ], d_in[4] vals f32[NNZ]
// Output: entity_agg [NE*64] ++ user_agg [NU*64], f32.

static constexpr int D  = 64;
static constexpr int D4 = D / 4;

static constexpr int MAX_NE = 50048;
static constexpr int MAX_NU = 100096;
static constexpr int ECAP = 128;    // entity degree: mean 40, tail ~70
static constexpr int UCAP = 64;     // user degree: mean 20, tail ~50
static constexpr int MAX_OVF = 8192;

__device__ int    g_ecnt[MAX_NE];
__device__ int    g_ucnt[MAX_NU];
__device__ float2 g_ebkt[(size_t)MAX_NE * ECAP];   // (user_idx bits, val)
__device__ float2 g_ubkt[(size_t)MAX_NU * UCAP];   // (entity_idx bits, val)
__device__ int    g_ovf_cnt;
__device__ float4 g_ovf[MAX_OVF];   // (seg | is_user<<30, nbr, val, unused)
// fp16 embeddings: one uint4 = 8 halves; row = 8 uint4 = 128 B.
__device__ uint4  g_uemb16[(size_t)MAX_NU * 8];
__device__ uint4  g_eemb16[(size_t)MAX_NE * 8];

__device__ __forceinline__ unsigned pack_h2(float a, float b) {
    __half2 h = __floats2half2_rn(a, b);
    return *reinterpret_cast<unsigned*>(&h);
}
__device__ __forceinline__ float2 unpack_h2(unsigned u) {
    __half2 h = *reinterpret_cast<__half2*>(&u);
    return __half22float2(h);
}
__device__ __forceinline__ __half2 as_h2(unsigned u) {
    return *reinterpret_cast<__half2*>(&u);
}

// ---------- phase 1: scatter + fp16 convert, roles interleaved ----------
// Block b is an edge block iff floor((b+1)*EB/TB) > floor(b*EB/TB).

__global__ void scatter_convert_kernel(const int* __restrict__ rows,
                                       const int* __restrict__ cols,
                                       const float* __restrict__ vals,
                                       int nnz,
                                       const float4* __restrict__ user_emb,
                                       const float4* __restrict__ entity_emb,
                                       int nu8, int ne8, int edge_blocks,
                                       int total_blocks) {
    int tid = threadIdx.x;
    int b = blockIdx.x;
    long long eidx  = ((long long)b * edge_blocks) / total_blocks;
    long long enext = ((long long)(b + 1) * edge_blocks) / total_blocks;
    if (enext > eidx) {
        // ---- edge block #eidx ----
        int e = (int)eidx * blockDim.x + tid;
        if (e >= nnz) return;
        int r = rows[e];
        int c = cols[e];
        float v = vals[e];

        int p = atomicAdd(&g_ecnt[c], 1);
        if (p < ECAP) {
            g_ebkt[(size_t)c * ECAP + p] = make_float2(__int_as_float(r), v);
        } else {
            int o = atomicAdd(&g_ovf_cnt, 1);
            if (o < MAX_OVF)
                g_ovf[o] = make_float4(__int_as_float(c), __int_as_float(r), v, 0.f);
        }

        int q = atomicAdd(&g_ucnt[r], 1);
        if (q < UCAP) {
            g_ubkt[(size_t)r * UCAP + q] = make_float2(__int_as_float(c), v);
        } else {
            int o = atomicAdd(&g_ovf_cnt, 1);
            if (o < MAX_OVF)
                g_ovf[o] = make_float4(__int_as_float(r | (1 << 30)), __int_as_float(c), v, 0.f);
        }
    } else {
        // ---- convert block: i indexes uint4 (two float4 of source) ----
        int cb = b - (int)enext;
        int i = cb * blockDim.x + tid;
        if (i < nu8) {
            float4 x0 = user_emb[i * 2];
            float4 x1 = user_emb[i * 2 + 1];
            g_uemb16[i] = make_uint4(pack_h2(x0.x, x0.y), pack_h2(x0.z, x0.w),
                                     pack_h2(x1.x, x1.y), pack_h2(x1.z, x1.w));
        } else {
            int j = i - nu8;
            if (j < ne8) {
                float4 x0 = entity_emb[j * 2];
                float4 x1 = entity_emb[j * 2 + 1];
                g_eemb16[j] = make_uint4(pack_h2(x0.x, x0.y), pack_h2(x0.z, x0.w),
                                         pack_h2(x1.x, x1.y), pack_h2(x1.z, x1.w));
            }
        }
    }
}

// ---------- phase 2: gather ----------
// 8 lanes per segment; lane owns 8 dims = one uint4 (16B, LDG.128).
// 4-edge chunks: per half2-group, two independent chains merged + fp32 flush
// (identical numerics to the 16-lane version).

__device__ __forceinline__ void chains4(__half2 v0, __half2 v1, __half2 v2,
                                        __half2 v3, unsigned g0, unsigned g1,
                                        unsigned g2, unsigned g3,
                                        float& ax, float& ay) {
    __half2 a = __hmul2(v0, as_h2(g0));
    __half2 b = __hmul2(v1, as_h2(g1));
    a = __hfma2(v2, as_h2(g2), a);
    b = __hfma2(v3, as_h2(g3), b);
    a = __hadd2(a, b);
    float2 f = __half22float2(a);
    ax += f.x;
    ay += f.y;
}

__global__ void __launch_bounds__(256)
gather_kernel(float4* __restrict__ entity_agg,
              float4* __restrict__ user_agg,
              int n_seg, int ne) {
    int gid  = blockIdx.x * blockDim.x + threadIdx.x;
    int s    = gid >> 3;
    int lane = gid & 7;
    if (s >= n_seg) return;

    const float2* __restrict__ bkt;
    const uint4* __restrict__ src16;
    float4* dst;           // two consecutive float4 per lane (8 dims)
    int cnt;
    int my_tag;
    if (s < ne) {
        cnt = g_ecnt[s];
        if (cnt > ECAP) cnt = ECAP;
        bkt = g_ebkt + (size_t)s * ECAP;
        src16 = g_uemb16;
        dst = entity_agg + (long long)s * D4;
        my_tag = s;
    } else {
        int u = s - ne;
        cnt = g_ucnt[u];
        if (cnt > UCAP) cnt = UCAP;
        bkt = g_ubkt + (size_t)u * UCAP;
        src16 = g_eemb16;
        dst = user_agg + (long long)u * D4;
        my_tag = u | (1 << 30);
    }

    float4 accA = make_float4(0.f, 0.f, 0.f, 0.f);   // dims 8l..8l+3
    float4 accB = make_float4(0.f, 0.f, 0.f, 0.f);   // dims 8l+4..8l+7
    int i = 0;
    for (; i + 3 < cnt; i += 4) {
        float2 e0 = bkt[i];
        float2 e1 = bkt[i + 1];
        float2 e2 = bkt[i + 2];
        float2 e3 = bkt[i + 3];
        uint4 x0 = src16[(size_t)__float_as_int(e0.x) * 8 + lane];
        uint4 x1 = src16[(size_t)__float_as_int(e1.x) * 8 + lane];
        uint4 x2 = src16[(size_t)__float_as_int(e2.x) * 8 + lane];
        uint4 x3 = src16[(size_t)__float_as_int(e3.x) * 8 + lane];

        __half2 v0 = __float2half2_rn(e0.y);
        __half2 v1 = __float2half2_rn(e1.y);
        __half2 v2 = __float2half2_rn(e2.y);
        __half2 v3 = __float2half2_rn(e3.y);

        chains4(v0, v1, v2, v3, x0.x, x1.x, x2.x, x3.x, accA.x, accA.y);
        chains4(v0, v1, v2, v3, x0.y, x1.y, x2.y, x3.y, accA.z, accA.w);
        chains4(v0, v1, v2, v3, x0.z, x1.z, x2.z, x3.z, accB.x, accB.y);
        chains4(v0, v1, v2, v3, x0.w, x1.w, x2.w, x3.w, accB.z, accB.w);
    }
    for (; i < cnt; i++) {
        float2 e0 = bkt[i];
        uint4 x0 = src16[(size_t)__float_as_int(e0.x) * 8 + lane];
        float2 a0 = unpack_h2(x0.x), a1 = unpack_h2(x0.y);
        float2 a2 = unpack_h2(x0.z), a3 = unpack_h2(x0.w);
        accA.x = fmaf(e0.y, a0.x, accA.x);
        accA.y = fmaf(e0.y, a0.y, accA.y);
        accA.z = fmaf(e0.y, a1.x, accA.z);
        accA.w = fmaf(e0.y, a1.y, accA.w);
        accB.x = fmaf(e0.y, a2.x, accB.x);
        accB.y = fmaf(e0.y, a2.y, accB.y);
        accB.z = fmaf(e0.y, a3.x, accB.z);
        accB.w = fmaf(e0.y, a3.y, accB.w);
    }

    // Inline overflow fixup: one broadcast load; body never runs in practice.
    int novf = g_ovf_cnt;
    if (novf > 0) {
        if (novf > MAX_OVF) novf = MAX_OVF;
        for (int o = 0; o < novf; o++) {
            float4 rec = g_ovf[o];
            if (__float_as_int(rec.x) == my_tag) {
                uint4 x = src16[(size_t)__float_as_int(rec.y) * 8 + lane];
                float2 a0 = unpack_h2(x.x), a1 = unpack_h2(x.y);
                float2 a2 = unpack_h2(x.z), a3 = unpack_h2(x.w);
                accA.x = fmaf(rec.z, a0.x, accA.x);
                accA.y = fmaf(rec.z, a0.y, accA.y);
                accA.z = fmaf(rec.z, a1.x, accA.z);
                accA.w = fmaf(rec.z, a1.y, accA.w);
                accB.x = fmaf(rec.z, a2.x, accB.x);
                accB.y = fmaf(rec.z, a2.y, accB.y);
                accB.z = fmaf(rec.z, a3.x, accB.z);
                accB.w = fmaf(rec.z, a3.y, accB.w);
            }
        }
    }

    dst[lane * 2]     = accA;
    dst[lane * 2 + 1] = accB;
}

// ---------- launch ----------

extern "C" void kernel_launch(void* const* d_in, const int* in_sizes, int n_in,
                              void* d_out, int out_size) {
    const float4* user_emb   = (const float4*)d_in[0];
    const float4* entity_emb = (const float4*)d_in[1];
    const int*    rows       = (const int*)d_in[2];
    const int*    cols       = (const int*)d_in[3];
    const float*  vals       = (const float*)d_in[4];

    int nu  = in_sizes[0] / D;
    int ne  = in_sizes[1] / D;
    int nnz = in_sizes[2];
    int n_seg = ne + nu;

    float* out = (float*)d_out;
    float4* entity_agg = (float4*)out;
    float4* user_agg   = (float4*)(out + (long long)ne * D);

    // Counter init via memset nodes (capture-legal, no allocation).
    void *p_ecnt = nullptr, *p_ucnt = nullptr, *p_ovf = nullptr;
    cudaGetSymbolAddress(&p_ecnt, g_ecnt);
    cudaGetSymbolAddress(&p_ucnt, g_ucnt);
    cudaGetSymbolAddress(&p_ovf,  g_ovf_cnt);
    cudaMemsetAsync(p_ecnt, 0, (size_t)ne * sizeof(int));
    cudaMemsetAsync(p_ucnt, 0, (size_t)nu * sizeof(int));
    cudaMemsetAsync(p_ovf,  0, sizeof(int));

    int T = 256;
    int edge_blocks = (nnz + T - 1) / T;
    int nu8 = nu * 8, ne8 = ne * 8;
    int conv_blocks = (nu8 + ne8 + T - 1) / T;
    int total_blocks = edge_blocks + conv_blocks;
    scatter_convert_kernel<<<total_blocks, T>>>(
        rows, cols, vals, nnz, user_emb, entity_emb, nu8, ne8,
        edge_blocks, total_blocks);

    long long total_threads = (long long)n_seg * 8;
    int gather_blocks = (int)((total_threads + T - 1) / T);
    gather_kernel<<<gather_blocks, T>>>(entity_agg, user_agg, n_seg, ne);
}

// round 16
// speedup vs baseline: 1.3081x; 1.0712x over previous
#include <cuda_runtime.h>
#include <cuda_fp16.h>
#include <cstdint>

// LightAggregator: bidirectional COO scatter-add as bucket-gather with
// fp16-compressed embedding reads and half2 inner-loop arithmetic
// (fp32 accumulation flushed every 4 edges).
//   entity_agg[c] = sum over edges (r,c,v): v * user_emb[r]
//   user_agg[r]   = sum over edges (r,c,v): v * entity_emb[c]
// Phase 1: scatter (2 edges/thread -> 4 independent ATOMG in flight, the
// latency-bound resource) into fixed-capacity buckets + fp16 table convert,
// block roles interleaved across the dispatch order.
// Phase 2: gather — 8 lanes per segment, lane owns 8 dims (uint4, LDG.128).
// Counters unified in one array -> single memset init node.
//
// Inputs: d_in[0] user_emb f32[NU*64], d_in[1] entity_emb f32[NE*64],
//         d_in[2] rows i32[NNZ], d_in[3] cols i32[NNZ], d_in[4] vals f32[NNZ]
// Output: entity_agg [NE*64] ++ user_agg [NU*64], f32.

static constexpr int D  = 64;
static constexpr int D4 = D / 4;

static constexpr int MAX_NE  = 50048;
static constexpr int MAX_NU  = 100096;
static constexpr int MAX_SEG = MAX_NE + MAX_NU + 8;
static constexpr int ECAP = 128;    // entity degree: mean 40, tail ~70
static constexpr int UCAP = 64;     // user degree: mean 20, tail ~50
static constexpr int MAX_OVF = 8192;

// g_cnt: [0,ne) entity counts, [ne,ne+nu) user counts, [n_seg] overflow count.
__device__ int    g_cnt[MAX_SEG];
__device__ float2 g_ebkt[(size_t)MAX_NE * ECAP];   // (user_idx bits, val)
__device__ float2 g_ubkt[(size_t)MAX_NU * UCAP];   // (entity_idx bits, val)
__device__ float4 g_ovf[MAX_OVF];   // (seg | is_user<<30, nbr, val, unused)
// fp16 embeddings: one uint4 = 8 halves; row = 8 uint4 = 128 B.
__device__ uint4  g_uemb16[(size_t)MAX_NU * 8];
__device__ uint4  g_eemb16[(size_t)MAX_NE * 8];

__device__ __forceinline__ unsigned pack_h2(float a, float b) {
    __half2 h = __floats2half2_rn(a, b);
    return *reinterpret_cast<unsigned*>(&h);
}
__device__ __forceinline__ float2 unpack_h2(unsigned u) {
    __half2 h = *reinterpret_cast<__half2*>(&u);
    return __half22float2(h);
}
__device__ __forceinline__ __half2 as_h2(unsigned u) {
    return *reinterpret_cast<__half2*>(&u);
}

// ---------- phase 1: scatter (2 edges/thread) + fp16 convert ----------
// Block b is an edge block iff floor((b+1)*EB/TB) > floor(b*EB/TB).

__device__ __forceinline__ void scatter_one(int r, int c, float v,
                                            int ne, int n_seg) {
    int p = atomicAdd(&g_cnt[c], 1);
    if (p < ECAP) {
        g_ebkt[(size_t)c * ECAP + p] = make_float2(__int_as_float(r), v);
    } else {
        int o = atomicAdd(&g_cnt[n_seg], 1);
        if (o < MAX_OVF)
            g_ovf[o] = make_float4(__int_as_float(c), __int_as_float(r), v, 0.f);
    }
    int q = atomicAdd(&g_cnt[ne + r], 1);
    if (q < UCAP) {
        g_ubkt[(size_t)r * UCAP + q] = make_float2(__int_as_float(c), v);
    } else {
        int o = atomicAdd(&g_cnt[n_seg], 1);
        if (o < MAX_OVF)
            g_ovf[o] = make_float4(__int_as_float(r | (1 << 30)), __int_as_float(c), v, 0.f);
    }
}

__global__ void scatter_convert_kernel(const int* __restrict__ rows,
                                       const int* __restrict__ cols,
                                       const float* __restrict__ vals,
                                       int nnz, int ne, int n_seg,
                                       const float4* __restrict__ user_emb,
                                       const float4* __restrict__ entity_emb,
                                       int nu8, int ne8, int edge_blocks,
                                       int total_blocks) {
    int tid = threadIdx.x;
    int b = blockIdx.x;
    long long eidx  = ((long long)b * edge_blocks) / total_blocks;
    long long enext = ((long long)(b + 1) * edge_blocks) / total_blocks;
    if (enext > eidx) {
        // ---- edge block #eidx: 512 edges, 2 per thread, coalesced ----
        int e0 = (int)eidx * 512 + tid;
        int e1 = e0 + 256;
        bool ok0 = e0 < nnz;
        bool ok1 = e1 < nnz;
        int r0 = 0, c0 = 0, r1 = 0, c1 = 0;
        float v0 = 0.f, v1 = 0.f;
        if (ok0) { r0 = rows[e0]; c0 = cols[e0]; v0 = vals[e0]; }
        if (ok1) { r1 = rows[e1]; c1 = cols[e1]; v1 = vals[e1]; }
        // Interleave the two edges' atomics for 4 independent ATOMG in flight.
        if (ok0 && ok1) {
            int p0 = atomicAdd(&g_cnt[c0], 1);
            int p1 = atomicAdd(&g_cnt[c1], 1);
            int q0 = atomicAdd(&g_cnt[ne + r0], 1);
            int q1 = atomicAdd(&g_cnt[ne + r1], 1);
            if (p0 < ECAP) {
                g_ebkt[(size_t)c0 * ECAP + p0] = make_float2(__int_as_float(r0), v0);
            } else {
                int o = atomicAdd(&g_cnt[n_seg], 1);
                if (o < MAX_OVF)
                    g_ovf[o] = make_float4(__int_as_float(c0), __int_as_float(r0), v0, 0.f);
            }
            if (p1 < ECAP) {
                g_ebkt[(size_t)c1 * ECAP + p1] = make_float2(__int_as_float(r1), v1);
            } else {
                int o = atomicAdd(&g_cnt[n_seg], 1);
                if (o < MAX_OVF)
                    g_ovf[o] = make_float4(__int_as_float(c1), __int_as_float(r1), v1, 0.f);
            }
            if (q0 < UCAP) {
                g_ubkt[(size_t)r0 * UCAP + q0] = make_float2(__int_as_float(c0), v0);
            } else {
                int o = atomicAdd(&g_cnt[n_seg], 1);
                if (o < MAX_OVF)
                    g_ovf[o] = make_float4(__int_as_float(r0 | (1 << 30)), __int_as_float(c0), v0, 0.f);
            }
            if (q1 < UCAP) {
                g_ubkt[(size_t)r1 * UCAP + q1] = make_float2(__int_as_float(c1), v1);
            } else {
                int o = atomicAdd(&g_cnt[n_seg], 1);
                if (o < MAX_OVF)
                    g_ovf[o] = make_float4(__int_as_float(r1 | (1 << 30)), __int_as_float(c1), v1, 0.f);
            }
        } else if (ok0) {
            scatter_one(r0, c0, v0, ne, n_seg);
        }
    } else {
        // ---- convert block: i indexes uint4 (two float4 of source) ----
        int cb = b - (int)enext;
        int i = cb * blockDim.x + tid;
        if (i < nu8) {
            float4 x0 = user_emb[i * 2];
            float4 x1 = user_emb[i * 2 + 1];
            g_uemb16[i] = make_uint4(pack_h2(x0.x, x0.y), pack_h2(x0.z, x0.w),
                                     pack_h2(x1.x, x1.y), pack_h2(x1.z, x1.w));
        } else {
            int j = i - nu8;
            if (j < ne8) {
                float4 x0 = entity_emb[j * 2];
                float4 x1 = entity_emb[j * 2 + 1];
                g_eemb16[j] = make_uint4(pack_h2(x0.x, x0.y), pack_h2(x0.z, x0.w),
                                         pack_h2(x1.x, x1.y), pack_h2(x1.z, x1.w));
            }
        }
    }
}

// ---------- phase 2: gather (R15 structure) ----------
// 8 lanes per segment; lane owns 8 dims = one uint4 (16B, LDG.128).

__device__ __forceinline__ void chains4(__half2 v0, __half2 v1, __half2 v2,
                                        __half2 v3, unsigned g0, unsigned g1,
                                        unsigned g2, unsigned g3,
                                        float& ax, float& ay) {
    __half2 a = __hmul2(v0, as_h2(g0));
    __half2 b = __hmul2(v1, as_h2(g1));
    a = __hfma2(v2, as_h2(g2), a);
    b = __hfma2(v3, as_h2(g3), b);
    a = __hadd2(a, b);
    float2 f = __half22float2(a);
    ax += f.x;
    ay += f.y;
}

__global__ void __launch_bounds__(256)
gather_kernel(float4* __restrict__ entity_agg,
              float4* __restrict__ user_agg,
              int n_seg, int ne) {
    int gid  = blockIdx.x * blockDim.x + threadIdx.x;
    int s    = gid >> 3;
    int lane = gid & 7;
    if (s >= n_seg) return;

    const float2* __restrict__ bkt;
    const uint4* __restrict__ src16;
    float4* dst;
    int cnt = g_cnt[s];
    int my_tag;
    if (s < ne) {
        if (cnt > ECAP) cnt = ECAP;
        bkt = g_ebkt + (size_t)s * ECAP;
        src16 = g_uemb16;
        dst = entity_agg + (long long)s * D4;
        my_tag = s;
    } else {
        int u = s - ne;
        if (cnt > UCAP) cnt = UCAP;
        bkt = g_ubkt + (size_t)u * UCAP;
        src16 = g_eemb16;
        dst = user_agg + (long long)u * D4;
        my_tag = u | (1 << 30);
    }

    float4 accA = make_float4(0.f, 0.f, 0.f, 0.f);
    float4 accB = make_float4(0.f, 0.f, 0.f, 0.f);
    int i = 0;
    for (; i + 3 < cnt; i += 4) {
        float2 e0 = bkt[i];
        float2 e1 = bkt[i + 1];
        float2 e2 = bkt[i + 2];
        float2 e3 = bkt[i + 3];
        uint4 x0 = src16[(size_t)__float_as_int(e0.x) * 8 + lane];
        uint4 x1 = src16[(size_t)__float_as_int(e1.x) * 8 + lane];
        uint4 x2 = src16[(size_t)__float_as_int(e2.x) * 8 + lane];
        uint4 x3 = src16[(size_t)__float_as_int(e3.x) * 8 + lane];

        __half2 v0 = __float2half2_rn(e0.y);
        __half2 v1 = __float2half2_rn(e1.y);
        __half2 v2 = __float2half2_rn(e2.y);
        __half2 v3 = __float2half2_rn(e3.y);

        chains4(v0, v1, v2, v3, x0.x, x1.x, x2.x, x3.x, accA.x, accA.y);
        chains4(v0, v1, v2, v3, x0.y, x1.y, x2.y, x3.y, accA.z, accA.w);
        chains4(v0, v1, v2, v3, x0.z, x1.z, x2.z, x3.z, accB.x, accB.y);
        chains4(v0, v1, v2, v3, x0.w, x1.w, x2.w, x3.w, accB.z, accB.w);
    }
    for (; i < cnt; i++) {
        float2 e0 = bkt[i];
        uint4 x0 = src16[(size_t)__float_as_int(e0.x) * 8 + lane];
        float2 a0 = unpack_h2(x0.x), a1 = unpack_h2(x0.y);
        float2 a2 = unpack_h2(x0.z), a3 = unpack_h2(x0.w);
        accA.x = fmaf(e0.y, a0.x, accA.x);
        accA.y = fmaf(e0.y, a0.y, accA.y);
        accA.z = fmaf(e0.y, a1.x, accA.z);
        accA.w = fmaf(e0.y, a1.y, accA.w);
        accB.x = fmaf(e0.y, a2.x, accB.x);
        accB.y = fmaf(e0.y, a2.y, accB.y);
        accB.z = fmaf(e0.y, a3.x, accB.z);
        accB.w = fmaf(e0.y, a3.y, accB.w);
    }

    // Inline overflow fixup: one broadcast load; body never runs in practice.
    int novf = g_cnt[n_seg];
    if (novf > 0) {
        if (novf > MAX_OVF) novf = MAX_OVF;
        for (int o = 0; o < novf; o++) {
            float4 rec = g_ovf[o];
            if (__float_as_int(rec.x) == my_tag) {
                uint4 x = src16[(size_t)__float_as_int(rec.y) * 8 + lane];
                float2 a0 = unpack_h2(x.x), a1 = unpack_h2(x.y);
                float2 a2 = unpack_h2(x.z), a3 = unpack_h2(x.w);
                accA.x = fmaf(rec.z, a0.x, accA.x);
                accA.y = fmaf(rec.z, a0.y, accA.y);
                accA.z = fmaf(rec.z, a1.x, accA.z);
                accA.w = fmaf(rec.z, a1.y, accA.w);
                accB.x = fmaf(rec.z, a2.x, accB.x);
                accB.y = fmaf(rec.z, a2.y, accB.y);
                accB.z = fmaf(rec.z, a3.x, accB.z);
                accB.w = fmaf(rec.z, a3.y, accB.w);
            }
        }
    }

    dst[lane * 2]     = accA;
    dst[lane * 2 + 1] = accB;
}

// ---------- launch ----------

extern "C" void kernel_launch(void* const* d_in, const int* in_sizes, int n_in,
                              void* d_out, int out_size) {
    const float4* user_emb   = (const float4*)d_in[0];
    const float4* entity_emb = (const float4*)d_in[1];
    const int*    rows       = (const int*)d_in[2];
    const int*    cols       = (const int*)d_in[3];
    const float*  vals       = (const float*)d_in[4];

    int nu  = in_sizes[0] / D;
    int ne  = in_sizes[1] / D;
    int nnz = in_sizes[2];
    int n_seg = ne + nu;

    float* out = (float*)d_out;
    float4* entity_agg = (float4*)out;
    float4* user_agg   = (float4*)(out + (long long)ne * D);

    // Single memset node: entity counts + user counts + overflow counter.
    void* p_cnt = nullptr;
    cudaGetSymbolAddress(&p_cnt, g_cnt);
    cudaMemsetAsync(p_cnt, 0, (size_t)(n_seg + 1) * sizeof(int));

    int T = 256;
    int edge_blocks = (nnz + 511) / 512;      // 2 edges/thread
    int nu8 = nu * 8, ne8 = ne * 8;
    int conv_blocks = (nu8 + ne8 + T - 1) / T;
    int total_blocks = edge_blocks + conv_blocks;
    scatter_convert_kernel<<<total_blocks, T>>>(
        rows, cols, vals, nnz, ne, n_seg, user_emb, entity_emb,
        nu8, ne8, edge_blocks, total_blocks);

    long long total_threads = (long long)n_seg * 8;
    int gather_blocks = (int)((total_threads + T - 1) / T);
    gather_kernel<<<gather_blocks, T>>>(entity_agg, user_agg, n_seg, ne);
}